// round 1
// baseline (speedup 1.0000x reference)
#include <cuda_runtime.h>
#include <cuda_bf16.h>
#include <math.h>

#define D 2048
#define H 8192
#define NL 4

// Scratch (device globals; no allocation allowed)
__device__ float g_x[D];     // current layer input
__device__ float g_rab[D];   // rsig * (a/b)
__device__ float g_sx[D];    // x + rwkv
__device__ float g_kk[H];    // relu(kffn@dx)^2
__device__ float g_r[D];     // sigmoid(rffn@xr)

__device__ __forceinline__ float warp_sum(float v) {
#pragma unroll
    for (int o = 16; o; o >>= 1) v += __shfl_xor_sync(0xffffffffu, v, o);
    return v;
}

// 256-thread block sum
__device__ __forceinline__ float block_sum(float v, float* sred) {
    v = warp_sum(v);
    int w = threadIdx.x >> 5, lane = threadIdx.x & 31;
    if (lane == 0) sred[w] = v;
    __syncthreads();
    float t = (threadIdx.x < 8) ? sred[threadIdx.x] : 0.f;
    if (w == 0) {
        t = warp_sum(t);
        if (lane == 0) sred[0] = t;
    }
    __syncthreads();
    float r = sred[0];
    __syncthreads();
    return r;
}

__global__ __launch_bounds__(256) void kcopy(const float* __restrict__ x) {
    int i = blockIdx.x * 256 + threadIdx.x;
    if (i < D) g_x[i] = x[i];
}

// Stage B: LN1 (fused, redundant per block) + rrk = key@xn + keymul@state_row + WKV epilogue.
// grid = 256 blocks x 256 threads; warp w of block b owns output index i = b*8 + w.
__global__ __launch_bounds__(256) void kB(
    const float* __restrict__ state,
    const float* __restrict__ ln1w, const float* __restrict__ ln1b,
    const float* __restrict__ key, const float* __restrict__ keymul,
    const float* __restrict__ td, const float* __restrict__ tf,
    float* __restrict__ out_state, int l)
{
    __shared__ __align__(16) float s_xn[D];
    __shared__ __align__(16) float s_sr[D];
    __shared__ float sred[9];
    int tid = threadIdx.x;
    const float* sr = state + (size_t)(5 * l + 0) * D;
    float lsum = 0.f;
    for (int i = tid; i < D; i += 256) {
        float xv = g_x[i];
        s_xn[i] = xv; lsum += xv;
        s_sr[i] = sr[i];
    }
    float m = block_sum(lsum, sred) * (1.f / D);
    float lv = 0.f;
    for (int i = tid; i < D; i += 256) { float d0 = s_xn[i] - m; lv += d0 * d0; }
    float var = block_sum(lv, sred) * (1.f / D);
    float rs = rsqrtf(var + 1e-5f);
    const float* w = ln1w + (size_t)l * D;
    const float* b = ln1b + (size_t)l * D;
    for (int i = tid; i < D; i += 256)
        s_xn[i] = (s_xn[i] - m) * rs * w[i] + b[i];
    __syncthreads();
    if (blockIdx.x == 0) {  // write xn state row
        float* xnrow = out_state + (size_t)(5 * l + 0) * D;
        for (int i = tid; i < D; i += 256) xnrow[i] = s_xn[i];
    }
    int warp = tid >> 5, lane = tid & 31;
    int i = blockIdx.x * 8 + warp;
    const float4* xn4 = (const float4*)s_xn;
    const float4* sr4 = (const float4*)s_sr;
    float acc[3];
#pragma unroll
    for (int j = 0; j < 3; j++) {
        const float4* kr = (const float4*)(key    + ((((size_t)l * 3 + j) * D + i) * D));
        const float4* mr = (const float4*)(keymul + ((((size_t)l * 3 + j) * D + i) * D));
        float a = 0.f;
        for (int t = lane; t < D / 4; t += 32) {
            float4 kk4 = kr[t], xx = xn4[t];
            float4 mm4 = mr[t], ss = sr4[t];
            a += kk4.x * xx.x + kk4.y * xx.y + kk4.z * xx.z + kk4.w * xx.w;
            a += mm4.x * ss.x + mm4.y * ss.y + mm4.z * ss.z + mm4.w * ss.w;
        }
        acc[j] = warp_sum(a);
    }
    if (lane == 0) {
        float k = acc[0], v = acc[1], rr = acc[2];
        float aa = state[(size_t)(5 * l + 1) * D + i];
        float bb = state[(size_t)(5 * l + 2) * D + i];
        float pp = state[(size_t)(5 * l + 3) * D + i];
        float tfi = tf[(size_t)l * D + i];
        float tdi = td[(size_t)l * D + i];
        float rsig = 1.f / (1.f + expf(-rr));
        float ww = tfi + k;
        float q = fmaxf(pp, ww);
        float e1 = expf(pp - q), e2 = expf(ww - q);
        float a_ = e1 * aa + e2 * v;
        float b_ = e1 * bb + e2;
        float ww2 = pp + tdi;
        float q2 = fmaxf(ww2, k);
        float f1 = expf(ww2 - q2), f2 = expf(k - q2);
        g_rab[i] = rsig * (a_ / b_);
        out_state[(size_t)(5 * l + 1) * D + i] = f1 * aa + f2 * v;
        out_state[(size_t)(5 * l + 2) * D + i] = f1 * bb + f2;
        out_state[(size_t)(5 * l + 3) * D + i] = q2;
    }
}

// Stage C: sx = x + outputv[l] @ g_rab.  grid = 256 x 256.
__global__ __launch_bounds__(256) void kC(const float* __restrict__ ow, int l)
{
    __shared__ __align__(16) float s_v[D];
    for (int i = threadIdx.x; i < D; i += 256) s_v[i] = g_rab[i];
    __syncthreads();
    int warp = threadIdx.x >> 5, lane = threadIdx.x & 31;
    int i = blockIdx.x * 8 + warp;
    const float4* r4 = (const float4*)(ow + ((size_t)l * D + i) * D);
    const float4* v4 = (const float4*)s_v;
    float a = 0.f;
    for (int t = lane; t < D / 4; t += 32) {
        float4 rr = r4[t], vv = v4[t];
        a += rr.x * vv.x + rr.y * vv.y + rr.z * vv.z + rr.w * vv.w;
    }
    a = warp_sum(a);
    if (lane == 0) g_sx[i] = g_x[i] + a;
}

// Stage E: LN2 fused (redundant per block) + kk = relu(kffn@dx)^2 and r = sigmoid(rffn@xr).
// grid = (H + D)/8 = 1280 blocks x 256 threads.
__global__ __launch_bounds__(256) void kE(
    const float* __restrict__ state,
    const float* __restrict__ ln2w, const float* __restrict__ ln2b,
    const float* __restrict__ tmk, const float* __restrict__ tmr,
    const float* __restrict__ kffn, const float* __restrict__ rffn,
    float* __restrict__ out_state, int l)
{
    __shared__ __align__(16) float s_dx[D];
    __shared__ __align__(16) float s_xr[D];
    __shared__ float sred[9];
    int tid = threadIdx.x;
    float lsum = 0.f;
    for (int i = tid; i < D; i += 256) { float v = g_sx[i]; s_dx[i] = v; lsum += v; }
    float m = block_sum(lsum, sred) * (1.f / D);
    float lv = 0.f;
    for (int i = tid; i < D; i += 256) { float d0 = s_dx[i] - m; lv += d0 * d0; }
    float var = block_sum(lv, sred) * (1.f / D);
    float rs = rsqrtf(var + 1e-5f);
    const float* w  = ln2w + (size_t)l * D;
    const float* b  = ln2b + (size_t)l * D;
    const float* sf = state + (size_t)(5 * l + 4) * D;
    const float* tk = tmk + (size_t)l * D;
    const float* tr = tmr + (size_t)l * D;
    for (int i = tid; i < D; i += 256) {
        float x2n = (s_dx[i] - m) * rs * w[i] + b[i];
        float sfi = sf[i];
        if (blockIdx.x == 0) out_state[(size_t)(5 * l + 4) * D + i] = x2n;
        s_xr[i] = x2n + sfi * tr[i];
        s_dx[i] = x2n + sfi * tk[i];
    }
    __syncthreads();
    int warp = tid >> 5, lane = tid & 31;
    int o = blockIdx.x * 8 + warp;
    if (o < H) {
        const float4* r4 = (const float4*)(kffn + ((size_t)l * H + o) * D);
        const float4* v4 = (const float4*)s_dx;
        float a = 0.f;
        for (int t = lane; t < D / 4; t += 32) {
            float4 rr = r4[t], vv = v4[t];
            a += rr.x * vv.x + rr.y * vv.y + rr.z * vv.z + rr.w * vv.w;
        }
        a = warp_sum(a);
        if (lane == 0) { float rl = fmaxf(a, 0.f); g_kk[o] = rl * rl; }
    } else {
        int i = o - H;
        const float4* r4 = (const float4*)(rffn + ((size_t)l * D + i) * D);
        const float4* v4 = (const float4*)s_xr;
        float a = 0.f;
        for (int t = lane; t < D / 4; t += 32) {
            float4 rr = r4[t], vv = v4[t];
            a += rr.x * vv.x + rr.y * vv.y + rr.z * vv.z + rr.w * vv.w;
        }
        a = warp_sum(a);
        if (lane == 0) g_r[i] = 1.f / (1.f + expf(-a));
    }
}

// Stage F: out = sx + r * (vffn[l] @ kk).  grid = 256 x 256. last!=0 -> write d_out x slot.
__global__ __launch_bounds__(256) void kF(const float* __restrict__ vffn,
                                          float* __restrict__ xout, int l, int last)
{
    __shared__ __align__(16) float s_kk[H];  // 32 KB
    for (int i = threadIdx.x; i < H; i += 256) s_kk[i] = g_kk[i];
    __syncthreads();
    int warp = threadIdx.x >> 5, lane = threadIdx.x & 31;
    int i = blockIdx.x * 8 + warp;
    const float4* r4 = (const float4*)(vffn + ((size_t)l * D + i) * H);
    const float4* v4 = (const float4*)s_kk;
    float a = 0.f;
    for (int t = lane; t < H / 4; t += 32) {
        float4 rr = r4[t], vv = v4[t];
        a += rr.x * vv.x + rr.y * vv.y + rr.z * vv.z + rr.w * vv.w;
    }
    a = warp_sum(a);
    if (lane == 0) {
        float val = g_sx[i] + g_r[i] * a;
        if (last) xout[i] = val;
        else g_x[i] = val;
    }
}

extern "C" void kernel_launch(void* const* d_in, const int* in_sizes, int n_in,
                              void* d_out, int out_size)
{
    const float* x      = (const float*)d_in[0];
    const float* state  = (const float*)d_in[1];
    const float* ln1w   = (const float*)d_in[2];
    const float* ln1b   = (const float*)d_in[3];
    const float* ln2w   = (const float*)d_in[4];
    const float* ln2b   = (const float*)d_in[5];
    const float* td     = (const float*)d_in[6];
    const float* tf     = (const float*)d_in[7];
    const float* key    = (const float*)d_in[8];
    const float* keymul = (const float*)d_in[9];
    const float* ow     = (const float*)d_in[10];
    const float* tmk    = (const float*)d_in[11];
    const float* tmr    = (const float*)d_in[12];
    const float* kffn   = (const float*)d_in[13];
    const float* rffn   = (const float*)d_in[14];
    const float* vffn   = (const float*)d_in[15];

    float* out       = (float*)d_out;
    float* out_x     = out;       // [D]
    float* out_state = out + D;   // [L*5*D]

    kcopy<<<(D + 255) / 256, 256>>>(x);
    for (int l = 0; l < NL; l++) {
        kB<<<D / 8, 256>>>(state, ln1w, ln1b, key, keymul, td, tf, out_state, l);
        kC<<<D / 8, 256>>>(ow, l);
        kE<<<(H + D) / 8, 256>>>(state, ln2w, ln2b, tmk, tmr, kffn, rffn, out_state, l);
        kF<<<D / 8, 256>>>(vffn, out_x, l, (l == NL - 1) ? 1 : 0);
    }
}

// round 2
// speedup vs baseline: 1.3002x; 1.3002x over previous
#include <cuda_runtime.h>
#include <cuda_bf16.h>
#include <math.h>

#define D 2048
#define H 8192
#define NL 4

// Scratch (device globals; no allocation allowed)
__device__ float g_x[D];     // current layer input
__device__ float g_rab[D];   // rsig * (a/b)
__device__ float g_sx[D];    // x + rwkv
__device__ float g_kk[H];    // relu(kffn@dx)^2
__device__ float g_r[D];     // sigmoid(rffn@xr)

__device__ __forceinline__ float warp_sum(float v) {
#pragma unroll
    for (int o = 16; o; o >>= 1) v += __shfl_xor_sync(0xffffffffu, v, o);
    return v;
}

__device__ __forceinline__ float d4(const float4 a, const float4 b) {
    return a.x * b.x + a.y * b.y + a.z * b.z + a.w * b.w;
}

// 256-thread block sum
__device__ __forceinline__ float block_sum(float v, float* sred) {
    v = warp_sum(v);
    int w = threadIdx.x >> 5, lane = threadIdx.x & 31;
    if (lane == 0) sred[w] = v;
    __syncthreads();
    float t = (threadIdx.x < 8) ? sred[threadIdx.x] : 0.f;
    if (w == 0) {
        t = warp_sum(t);
        if (lane == 0) sred[0] = t;
    }
    __syncthreads();
    float r = sred[0];
    __syncthreads();
    return r;
}

// Unrolled streaming dot: row (global, no reuse) . vec (smem). n4 = row len / 4,
// must be a multiple of 128 (i.e., row length multiple of 512 floats).
__device__ __forceinline__ float dot_stream(const float4* __restrict__ r4,
                                            const float4* __restrict__ s4,
                                            int n4, int lane) {
    float a0 = 0.f, a1 = 0.f, a2 = 0.f, a3 = 0.f;
    for (int t = lane; t < n4; t += 128) {
        float4 r0 = __ldcs(r4 + t);
        float4 r1 = __ldcs(r4 + t + 32);
        float4 r2 = __ldcs(r4 + t + 64);
        float4 r3 = __ldcs(r4 + t + 96);
        a0 += d4(r0, s4[t]);
        a1 += d4(r1, s4[t + 32]);
        a2 += d4(r2, s4[t + 64]);
        a3 += d4(r3, s4[t + 96]);
    }
    return warp_sum(a0 + a1 + a2 + a3);
}

__global__ __launch_bounds__(256) void kcopy(const float* __restrict__ x) {
    int i = blockIdx.x * 256 + threadIdx.x;
    if (i < D) g_x[i] = x[i];
}

// Stage B: LN1 (fused, redundant per block) + rrk = key@xn + keymul@state_row + WKV epilogue.
// grid = 256 blocks x 256 threads; warp w of block b owns output index i = b*8 + w.
__global__ __launch_bounds__(256) void kB(
    const float* __restrict__ state,
    const float* __restrict__ ln1w, const float* __restrict__ ln1b,
    const float* __restrict__ key, const float* __restrict__ keymul,
    const float* __restrict__ td, const float* __restrict__ tf,
    float* __restrict__ out_state, int l)
{
    __shared__ __align__(16) float s_xn[D];
    __shared__ __align__(16) float s_sr[D];
    __shared__ float sred[9];
    int tid = threadIdx.x;
    const float* sr = state + (size_t)(5 * l + 0) * D;
    float lsum = 0.f;
    for (int i = tid; i < D; i += 256) {
        float xv = g_x[i];
        s_xn[i] = xv; lsum += xv;
        s_sr[i] = sr[i];
    }
    float m = block_sum(lsum, sred) * (1.f / D);
    float lv = 0.f;
    for (int i = tid; i < D; i += 256) { float d0 = s_xn[i] - m; lv += d0 * d0; }
    float var = block_sum(lv, sred) * (1.f / D);
    float rs = rsqrtf(var + 1e-5f);
    const float* w = ln1w + (size_t)l * D;
    const float* b = ln1b + (size_t)l * D;
    for (int i = tid; i < D; i += 256)
        s_xn[i] = (s_xn[i] - m) * rs * w[i] + b[i];
    __syncthreads();
    if (blockIdx.x == 0) {  // write xn state row
        float* xnrow = out_state + (size_t)(5 * l + 0) * D;
        for (int i = tid; i < D; i += 256) xnrow[i] = s_xn[i];
    }
    int warp = tid >> 5, lane = tid & 31;
    int i = blockIdx.x * 8 + warp;
    const float4* xn4 = (const float4*)s_xn;
    const float4* sr4 = (const float4*)s_sr;
    float acc[3];
#pragma unroll
    for (int j = 0; j < 3; j++) {
        const float4* kr = (const float4*)(key    + ((((size_t)l * 3 + j) * D + i) * D));
        const float4* mr = (const float4*)(keymul + ((((size_t)l * 3 + j) * D + i) * D));
        float a0 = 0.f, a1 = 0.f, a2 = 0.f, a3 = 0.f;
        float b0 = 0.f, b1 = 0.f, b2 = 0.f, b3 = 0.f;
        for (int t = lane; t < D / 4; t += 128) {
            float4 k0 = __ldcs(kr + t);
            float4 k1 = __ldcs(kr + t + 32);
            float4 k2 = __ldcs(kr + t + 64);
            float4 k3 = __ldcs(kr + t + 96);
            float4 m0 = __ldcs(mr + t);
            float4 m1 = __ldcs(mr + t + 32);
            float4 m2 = __ldcs(mr + t + 64);
            float4 m3 = __ldcs(mr + t + 96);
            a0 += d4(k0, xn4[t]);
            a1 += d4(k1, xn4[t + 32]);
            a2 += d4(k2, xn4[t + 64]);
            a3 += d4(k3, xn4[t + 96]);
            b0 += d4(m0, sr4[t]);
            b1 += d4(m1, sr4[t + 32]);
            b2 += d4(m2, sr4[t + 64]);
            b3 += d4(m3, sr4[t + 96]);
        }
        acc[j] = warp_sum(a0 + a1 + a2 + a3 + b0 + b1 + b2 + b3);
    }
    if (lane == 0) {
        float k = acc[0], v = acc[1], rr = acc[2];
        float aa = state[(size_t)(5 * l + 1) * D + i];
        float bb = state[(size_t)(5 * l + 2) * D + i];
        float pp = state[(size_t)(5 * l + 3) * D + i];
        float tfi = tf[(size_t)l * D + i];
        float tdi = td[(size_t)l * D + i];
        float rsig = 1.f / (1.f + expf(-rr));
        float ww = tfi + k;
        float q = fmaxf(pp, ww);
        float e1 = expf(pp - q), e2 = expf(ww - q);
        float a_ = e1 * aa + e2 * v;
        float b_ = e1 * bb + e2;
        float ww2 = pp + tdi;
        float q2 = fmaxf(ww2, k);
        float f1 = expf(ww2 - q2), f2 = expf(k - q2);
        g_rab[i] = rsig * (a_ / b_);
        out_state[(size_t)(5 * l + 1) * D + i] = f1 * aa + f2 * v;
        out_state[(size_t)(5 * l + 2) * D + i] = f1 * bb + f2;
        out_state[(size_t)(5 * l + 3) * D + i] = q2;
    }
}

// Stage C: sx = x + outputv[l] @ g_rab.  grid = 256 x 256.
__global__ __launch_bounds__(256) void kC(const float* __restrict__ ow, int l)
{
    __shared__ __align__(16) float s_v[D];
    for (int i = threadIdx.x; i < D; i += 256) s_v[i] = g_rab[i];
    __syncthreads();
    int warp = threadIdx.x >> 5, lane = threadIdx.x & 31;
    int i = blockIdx.x * 8 + warp;
    const float4* r4 = (const float4*)(ow + ((size_t)l * D + i) * D);
    float a = dot_stream(r4, (const float4*)s_v, D / 4, lane);
    if (lane == 0) g_sx[i] = g_x[i] + a;
}

// Stage E: LN2 fused (redundant per block) + kk = relu(kffn@dx)^2 and r = sigmoid(rffn@xr).
// grid = (H + D)/8 = 1280 blocks x 256 threads.
__global__ __launch_bounds__(256) void kE(
    const float* __restrict__ state,
    const float* __restrict__ ln2w, const float* __restrict__ ln2b,
    const float* __restrict__ tmk, const float* __restrict__ tmr,
    const float* __restrict__ kffn, const float* __restrict__ rffn,
    float* __restrict__ out_state, int l)
{
    __shared__ __align__(16) float s_dx[D];
    __shared__ __align__(16) float s_xr[D];
    __shared__ float sred[9];
    int tid = threadIdx.x;
    float lsum = 0.f;
    for (int i = tid; i < D; i += 256) { float v = g_sx[i]; s_dx[i] = v; lsum += v; }
    float m = block_sum(lsum, sred) * (1.f / D);
    float lv = 0.f;
    for (int i = tid; i < D; i += 256) { float d0 = s_dx[i] - m; lv += d0 * d0; }
    float var = block_sum(lv, sred) * (1.f / D);
    float rs = rsqrtf(var + 1e-5f);
    const float* w  = ln2w + (size_t)l * D;
    const float* b  = ln2b + (size_t)l * D;
    const float* sf = state + (size_t)(5 * l + 4) * D;
    const float* tk = tmk + (size_t)l * D;
    const float* tr = tmr + (size_t)l * D;
    for (int i = tid; i < D; i += 256) {
        float x2n = (s_dx[i] - m) * rs * w[i] + b[i];
        float sfi = sf[i];
        if (blockIdx.x == 0) out_state[(size_t)(5 * l + 4) * D + i] = x2n;
        s_xr[i] = x2n + sfi * tr[i];
        s_dx[i] = x2n + sfi * tk[i];
    }
    __syncthreads();
    int warp = tid >> 5, lane = tid & 31;
    int o = blockIdx.x * 8 + warp;
    if (o < H) {
        const float4* r4 = (const float4*)(kffn + ((size_t)l * H + o) * D);
        float a = dot_stream(r4, (const float4*)s_dx, D / 4, lane);
        if (lane == 0) { float rl = fmaxf(a, 0.f); g_kk[o] = rl * rl; }
    } else {
        int i = o - H;
        const float4* r4 = (const float4*)(rffn + ((size_t)l * D + i) * D);
        float a = dot_stream(r4, (const float4*)s_xr, D / 4, lane);
        if (lane == 0) g_r[i] = 1.f / (1.f + expf(-a));
    }
}

// Stage F: out = sx + r * (vffn[l] @ kk).  grid = 256 x 256. last!=0 -> write d_out x slot.
__global__ __launch_bounds__(256) void kF(const float* __restrict__ vffn,
                                          float* __restrict__ xout, int l, int last)
{
    __shared__ __align__(16) float s_kk[H];  // 32 KB
    for (int i = threadIdx.x; i < H; i += 256) s_kk[i] = g_kk[i];
    __syncthreads();
    int warp = threadIdx.x >> 5, lane = threadIdx.x & 31;
    int i = blockIdx.x * 8 + warp;
    const float4* r4 = (const float4*)(vffn + ((size_t)l * D + i) * H);
    float a = dot_stream(r4, (const float4*)s_kk, H / 4, lane);
    if (lane == 0) {
        float val = g_sx[i] + g_r[i] * a;
        if (last) xout[i] = val;
        else g_x[i] = val;
    }
}

extern "C" void kernel_launch(void* const* d_in, const int* in_sizes, int n_in,
                              void* d_out, int out_size)
{
    const float* x      = (const float*)d_in[0];
    const float* state  = (const float*)d_in[1];
    const float* ln1w   = (const float*)d_in[2];
    const float* ln1b   = (const float*)d_in[3];
    const float* ln2w   = (const float*)d_in[4];
    const float* ln2b   = (const float*)d_in[5];
    const float* td     = (const float*)d_in[6];
    const float* tf     = (const float*)d_in[7];
    const float* key    = (const float*)d_in[8];
    const float* keymul = (const float*)d_in[9];
    const float* ow     = (const float*)d_in[10];
    const float* tmk    = (const float*)d_in[11];
    const float* tmr    = (const float*)d_in[12];
    const float* kffn   = (const float*)d_in[13];
    const float* rffn   = (const float*)d_in[14];
    const float* vffn   = (const float*)d_in[15];

    float* out       = (float*)d_out;
    float* out_x     = out;       // [D]
    float* out_state = out + D;   // [L*5*D]

    kcopy<<<(D + 255) / 256, 256>>>(x);
    for (int l = 0; l < NL; l++) {
        kB<<<D / 8, 256>>>(state, ln1w, ln1b, key, keymul, td, tf, out_state, l);
        kC<<<D / 8, 256>>>(ow, l);
        kE<<<(H + D) / 8, 256>>>(state, ln2w, ln2b, tmk, tmr, kffn, rffn, out_state, l);
        kF<<<D / 8, 256>>>(vffn, out_x, l, (l == NL - 1) ? 1 : 0);
    }
}